// round 1
// baseline (speedup 1.0000x reference)
#include <cuda_runtime.h>

#define NN 50000
#define HH 64
#define MAILW 84   // 64 u-sum + 16 ef-sum + 1 deg + 3 pad  (21 float4)

// Scratch (no runtime allocation allowed)
__device__ __align__(16) float g_u[NN * HH];     // h @ W1d^T
__device__ __align__(16) float g_p[NN * HH];     // nf @ W1a^T
__device__ __align__(16) float g_q[NN * HH];     // nf @ W1b^T
__device__ __align__(16) float g_mail[NN * MAILW];

// ---------------------------------------------------------------------------
// Kernel 1: zero mailbox; compute u = h@W1d^T, p = nf@W1a^T, q = nf@W1b^T
// W1 is [64 out, 144 in]; in-blocks: a=[0,32) b=[32,64) c=[64,80) d=[80,144)
// ---------------------------------------------------------------------------
__global__ __launch_bounds__(256) void precompute_kernel(
    const float* __restrict__ h, const float* __restrict__ nf,
    const float* __restrict__ W1, int N)
{
    __shared__ float sW1aT[32 * 64];
    __shared__ float sW1bT[32 * 64];
    __shared__ float sW1dT[64 * 64];

    // zero mailbox (grid-stride float4 stores)
    {
        float4* m4 = reinterpret_cast<float4*>(g_mail);
        int total = NN * (MAILW / 4);
        int tid = blockIdx.x * blockDim.x + threadIdx.x;
        int stride = gridDim.x * blockDim.x;
        float4 z = make_float4(0.f, 0.f, 0.f, 0.f);
        for (int i = tid; i < total; i += stride) m4[i] = z;
    }

    // load W1 transposed into shared
    for (int idx = threadIdx.x; idx < 64 * 144; idx += blockDim.x) {
        int j = idx / 144;
        int k = idx % 144;
        float w = W1[idx];
        if (k < 32)       sW1aT[k * 64 + j] = w;
        else if (k < 64)  sW1bT[(k - 32) * 64 + j] = w;
        else if (k >= 80) sW1dT[(k - 80) * 64 + j] = w;
    }
    __syncthreads();

    int j   = threadIdx.x & 63;       // output index
    int sub = threadIdx.x >> 6;       // node-within-block (0..3)
    int npb = blockDim.x >> 6;        // 4 nodes per block per sweep

    for (int n = blockIdx.x * npb + sub; n < N; n += gridDim.x * npb) {
        const float4* h4  = reinterpret_cast<const float4*>(h)  + n * 16;
        const float4* nf4 = reinterpret_cast<const float4*>(nf) + n * 8;

        float accu = 0.f;
        #pragma unroll
        for (int kk = 0; kk < 16; kk++) {
            float4 hv = __ldg(&h4[kk]);
            int k = kk * 4;
            accu = fmaf(hv.x, sW1dT[(k + 0) * 64 + j], accu);
            accu = fmaf(hv.y, sW1dT[(k + 1) * 64 + j], accu);
            accu = fmaf(hv.z, sW1dT[(k + 2) * 64 + j], accu);
            accu = fmaf(hv.w, sW1dT[(k + 3) * 64 + j], accu);
        }
        float accp = 0.f, accq = 0.f;
        #pragma unroll
        for (int kk = 0; kk < 8; kk++) {
            float4 v = __ldg(&nf4[kk]);
            int k = kk * 4;
            accp = fmaf(v.x, sW1aT[(k + 0) * 64 + j], accp);
            accp = fmaf(v.y, sW1aT[(k + 1) * 64 + j], accp);
            accp = fmaf(v.z, sW1aT[(k + 2) * 64 + j], accp);
            accp = fmaf(v.w, sW1aT[(k + 3) * 64 + j], accp);
            accq = fmaf(v.x, sW1bT[(k + 0) * 64 + j], accq);
            accq = fmaf(v.y, sW1bT[(k + 1) * 64 + j], accq);
            accq = fmaf(v.z, sW1bT[(k + 2) * 64 + j], accq);
            accq = fmaf(v.w, sW1bT[(k + 3) * 64 + j], accq);
        }
        g_u[n * 64 + j] = accu;
        g_p[n * 64 + j] = accp;
        g_q[n * 64 + j] = accq;
    }
}

// ---------------------------------------------------------------------------
// Kernel 2: warp per edge. Fused vector-atomic scatter of [u[src], ef[e], 1]
// into mailbox[dst] (21 float4 lanes, one predicated RED per edge).
// ---------------------------------------------------------------------------
__global__ __launch_bounds__(256) void edge_kernel(
    const int* __restrict__ src, const int* __restrict__ dst,
    const float* __restrict__ ef, int E)
{
    int lane = threadIdx.x & 31;
    int gw = (blockIdx.x * blockDim.x + threadIdx.x) >> 5;
    int nw = (gridDim.x * blockDim.x) >> 5;

    const float4* u4  = reinterpret_cast<const float4*>(g_u);
    const float4* ef4 = reinterpret_cast<const float4*>(ef);
    float4* mail4 = reinterpret_cast<float4*>(g_mail);

    for (int e = gw; e < E; e += nw) {
        int s = __ldg(&src[e]);
        int d = __ldg(&dst[e]);
        if (lane < 21) {
            float4 v;
            if (lane < 16)      v = __ldg(&u4[s * 16 + lane]);
            else if (lane < 20) v = __ldg(&ef4[e * 4 + (lane - 16)]);
            else                v = make_float4(1.f, 0.f, 0.f, 0.f);
            atomicAdd(&mail4[d * 21 + lane], v);
        }
    }
}

// ---------------------------------------------------------------------------
// Kernel 3: warp per node. y = mail_u + p + deg*q + W1c@mail_ef; relu;
// out = (deg>0) ? y@W2^T : h
// ---------------------------------------------------------------------------
__global__ __launch_bounds__(256) void finalize_kernel(
    const float* __restrict__ h, const float* __restrict__ W1,
    const float* __restrict__ W2, float* __restrict__ out, int N)
{
    __shared__ float sW1cT[16 * 64];  // [k][j]
    __shared__ float sW2T[64 * 64];   // [j][i]

    for (int idx = threadIdx.x; idx < 64 * 16; idx += blockDim.x) {
        int j = idx / 16, k = idx % 16;
        sW1cT[k * 64 + j] = W1[j * 144 + 64 + k];
    }
    for (int idx = threadIdx.x; idx < 64 * 64; idx += blockDim.x) {
        int i = idx / 64, j = idx % 64;
        sW2T[j * 64 + i] = W2[idx];
    }
    __syncthreads();

    int lane = threadIdx.x & 31;
    int gw = (blockIdx.x * blockDim.x + threadIdx.x) >> 5;
    int nw = (gridDim.x * blockDim.x) >> 5;

    for (int n = gw; n < N; n += nw) {
        const float* mail = g_mail + n * MAILW;
        float dg = mail[80];

        int j0 = lane, j1 = lane + 32;
        float y0 = mail[j0] + g_p[n * 64 + j0] + dg * g_q[n * 64 + j0];
        float y1 = mail[j1] + g_p[n * 64 + j1] + dg * g_q[n * 64 + j1];

        #pragma unroll
        for (int k = 0; k < 16; k++) {
            float mk = mail[64 + k];
            y0 = fmaf(mk, sW1cT[k * 64 + j0], y0);
            y1 = fmaf(mk, sW1cT[k * 64 + j1], y1);
        }
        y0 = fmaxf(y0, 0.f);
        y1 = fmaxf(y1, 0.f);

        float o0 = 0.f, o1 = 0.f;
        #pragma unroll
        for (int j = 0; j < 64; j++) {
            float yj = __shfl_sync(0xffffffffu, (j < 32) ? y0 : y1, j & 31);
            o0 = fmaf(yj, sW2T[j * 64 + lane], o0);
            o1 = fmaf(yj, sW2T[j * 64 + lane + 32], o1);
        }

        if (dg > 0.f) {
            out[n * 64 + lane]      = o0;
            out[n * 64 + lane + 32] = o1;
        } else {
            out[n * 64 + lane]      = h[n * 64 + lane];
            out[n * 64 + lane + 32] = h[n * 64 + lane + 32];
        }
    }
}

// ---------------------------------------------------------------------------
extern "C" void kernel_launch(void* const* d_in, const int* in_sizes, int n_in,
                              void* d_out, int out_size)
{
    const float* h  = (const float*)d_in[0];
    const float* nf = (const float*)d_in[1];
    const float* ef = (const float*)d_in[2];
    const int*  src = (const int*)d_in[3];
    const int*  dst = (const int*)d_in[4];
    const float* W1 = (const float*)d_in[5];
    const float* W2 = (const float*)d_in[6];
    float* out = (float*)d_out;

    int N = in_sizes[1] / 32;   // nf is [N, 32]
    int E = in_sizes[3];        // src is [E]

    precompute_kernel<<<592, 256>>>(h, nf, W1, N);
    edge_kernel<<<1184, 256>>>(src, dst, ef, E);
    finalize_kernel<<<1184, 256>>>(h, W1, W2, out, N);
}

// round 3
// speedup vs baseline: 1.1082x; 1.1082x over previous
#include <cuda_runtime.h>

#define NN 50000
#define HH 64
#define MAILW 84   // 64 u-sum + 16 ef-sum + 1 deg + 3 pad  (21 float4)

// Scratch (no runtime allocation allowed)
__device__ __align__(16) float g_u[NN * HH];     // h @ W1d^T
__device__ __align__(16) float g_p[NN * HH];     // nf @ W1a^T
__device__ __align__(16) float g_q[NN * HH];     // nf @ W1b^T
__device__ __align__(16) float g_mail[NN * MAILW];

#define COMP(v, c) ((c) == 0 ? (v).x : (c) == 1 ? (v).y : (c) == 2 ? (v).z : (v).w)

// ---------------------------------------------------------------------------
// Kernel 1: zero mailbox; compute u = h@W1d^T, p = nf@W1a^T, q = nf@W1b^T
// W1 is [64 out, 144 in]; in-blocks: a=[0,32) b=[32,64) c=[64,80) d=[80,144)
// Register-blocked: each thread handles 8 nodes for one output j.
// Weight smem reads amortized 8x -> FMA-pipe bound instead of LDS-bound.
// ---------------------------------------------------------------------------
__global__ __launch_bounds__(256) void precompute_kernel(
    const float* __restrict__ h, const float* __restrict__ nf,
    const float* __restrict__ W1, int N)
{
    __shared__ float sA[32 * 64];   // W1a^T [k][j]
    __shared__ float sB[32 * 64];   // W1b^T [k][j]
    __shared__ float sD[64 * 64];   // W1d^T [k][j]

    // zero mailbox (grid-stride float4 stores)
    {
        float4* m4 = reinterpret_cast<float4*>(g_mail);
        int total = NN * (MAILW / 4);
        int tid = blockIdx.x * blockDim.x + threadIdx.x;
        int stride = gridDim.x * blockDim.x;
        float4 z = make_float4(0.f, 0.f, 0.f, 0.f);
        for (int i = tid; i < total; i += stride) m4[i] = z;
    }

    // load W1 transposed into shared
    for (int idx = threadIdx.x; idx < 64 * 144; idx += blockDim.x) {
        int j = idx / 144;
        int k = idx % 144;
        float w = W1[idx];
        if (k < 32)       sA[k * 64 + j] = w;
        else if (k < 64)  sB[(k - 32) * 64 + j] = w;
        else if (k >= 80) sD[(k - 80) * 64 + j] = w;
    }
    __syncthreads();

    int j   = threadIdx.x & 63;        // output index
    int grp = threadIdx.x >> 6;        // 0..3
    int gid = blockIdx.x * 4 + grp;    // node-group id (8 nodes each)
    int n0  = gid * 8;
    if (n0 >= N) return;

    float accp[8], accq[8], accu[8];
    #pragma unroll
    for (int m = 0; m < 8; m++) { accp[m] = 0.f; accq[m] = 0.f; accu[m] = 0.f; }

    const float4* nf4 = reinterpret_cast<const float4*>(nf) + n0 * 8;
    const float4* h4  = reinterpret_cast<const float4*>(h)  + n0 * 16;

    #pragma unroll
    for (int kk = 0; kk < 8; kk++) {
        float4 xv[8];
        #pragma unroll
        for (int m = 0; m < 8; m++) xv[m] = __ldg(&nf4[m * 8 + kk]);
        #pragma unroll
        for (int c = 0; c < 4; c++) {
            float wa = sA[(kk * 4 + c) * 64 + j];
            float wb = sB[(kk * 4 + c) * 64 + j];
            #pragma unroll
            for (int m = 0; m < 8; m++) {
                float x = COMP(xv[m], c);
                accp[m] = fmaf(x, wa, accp[m]);
                accq[m] = fmaf(x, wb, accq[m]);
            }
        }
    }

    #pragma unroll
    for (int kk = 0; kk < 16; kk++) {
        float4 xv[8];
        #pragma unroll
        for (int m = 0; m < 8; m++) xv[m] = __ldg(&h4[m * 16 + kk]);
        #pragma unroll
        for (int c = 0; c < 4; c++) {
            float wd = sD[(kk * 4 + c) * 64 + j];
            #pragma unroll
            for (int m = 0; m < 8; m++) {
                float x = COMP(xv[m], c);
                accu[m] = fmaf(x, wd, accu[m]);
            }
        }
    }

    #pragma unroll
    for (int m = 0; m < 8; m++) {
        int n = n0 + m;
        g_p[n * 64 + j] = accp[m];
        g_q[n * 64 + j] = accq[m];
        g_u[n * 64 + j] = accu[m];
    }
}

// ---------------------------------------------------------------------------
// Kernel 2: thread per (edge, float4-chunk). Full lane utilization.
// Scatters [u[src] (16 chunks), ef[e] (4 chunks), deg (1 chunk)] into
// mailbox[dst] via vector RED.
// ---------------------------------------------------------------------------
__global__ __launch_bounds__(256) void edge_kernel(
    const int* __restrict__ src, const int* __restrict__ dst,
    const float* __restrict__ ef, int E)
{
    int gid = blockIdx.x * blockDim.x + threadIdx.x;
    int total = E * 21;
    if (gid >= total) return;

    int e = gid / 21;
    int c = gid - e * 21;

    int s = __ldg(&src[e]);
    int d = __ldg(&dst[e]);

    const float4* u4  = reinterpret_cast<const float4*>(g_u);
    const float4* ef4 = reinterpret_cast<const float4*>(ef);
    float4* mail4 = reinterpret_cast<float4*>(g_mail);

    float4 v;
    if (c < 16)      v = __ldg(&u4[s * 16 + c]);
    else if (c < 20) v = __ldg(&ef4[e * 4 + (c - 16)]);
    else             v = make_float4(1.f, 0.f, 0.f, 0.f);
    atomicAdd(&mail4[d * 21 + c], v);
}

// ---------------------------------------------------------------------------
// Kernel 3: warp per 4 nodes, register-blocked W2 GEMM with smem y staging.
// y = mail_u + p + deg*q + W1c@mail_ef; relu; out = (deg>0) ? y@W2^T : h
// ---------------------------------------------------------------------------
__global__ __launch_bounds__(256) void finalize_kernel(
    const float* __restrict__ h, const float* __restrict__ W1,
    const float* __restrict__ W2, float* __restrict__ out, int N)
{
    __shared__ float sW1cT[16 * 64];   // [k][j]
    __shared__ float sW2T[64 * 64];    // [j][i]
    __shared__ float sY[8][4 * 64];    // per-warp staging: 4 nodes x 64

    for (int idx = threadIdx.x; idx < 64 * 16; idx += blockDim.x) {
        int j = idx / 16, k = idx % 16;
        sW1cT[k * 64 + j] = W1[j * 144 + 64 + k];
    }
    for (int idx = threadIdx.x; idx < 64 * 64; idx += blockDim.x) {
        int i = idx / 64, j = idx % 64;
        sW2T[j * 64 + i] = W2[idx];
    }
    __syncthreads();

    int lane = threadIdx.x & 31;
    int warp = threadIdx.x >> 5;
    int gw = (blockIdx.x * blockDim.x + threadIdx.x) >> 5;
    int nb = gw * 4;                    // 4 nodes per warp
    if (nb >= N) return;
    int cnt = min(4, N - nb);

    float dgv[4];

    // ---- phase 1: build y for up to 4 nodes, stage relu(y) in smem ----
    for (int m = 0; m < cnt; m++) {
        int n = nb + m;
        const float* mail = g_mail + n * MAILW;
        float dg = __ldg(&mail[80]);
        dgv[m] = dg;

        float y0 = mail[lane]      + g_p[n * 64 + lane]      + dg * g_q[n * 64 + lane];
        float y1 = mail[lane + 32] + g_p[n * 64 + lane + 32] + dg * g_q[n * 64 + lane + 32];

        #pragma unroll
        for (int k = 0; k < 16; k++) {
            float mk = __ldg(&mail[64 + k]);
            y0 = fmaf(mk, sW1cT[k * 64 + lane],      y0);
            y1 = fmaf(mk, sW1cT[k * 64 + lane + 32], y1);
        }
        sY[warp][m * 64 + lane]      = fmaxf(y0, 0.f);
        sY[warp][m * 64 + lane + 32] = fmaxf(y1, 0.f);
    }
    __syncwarp();

    // ---- phase 2: out = y @ W2^T, weights amortized over 4 nodes ----
    float o0[4] = {0.f, 0.f, 0.f, 0.f};
    float o1[4] = {0.f, 0.f, 0.f, 0.f};
    #pragma unroll
    for (int j = 0; j < 64; j++) {
        float w0 = sW2T[j * 64 + lane];
        float w1 = sW2T[j * 64 + lane + 32];
        #pragma unroll
        for (int m = 0; m < 4; m++) {
            float yj = sY[warp][m * 64 + j];
            o0[m] = fmaf(yj, w0, o0[m]);
            o1[m] = fmaf(yj, w1, o1[m]);
        }
    }

    for (int m = 0; m < cnt; m++) {
        int n = nb + m;
        if (dgv[m] > 0.f) {
            out[n * 64 + lane]      = o0[m];
            out[n * 64 + lane + 32] = o1[m];
        } else {
            out[n * 64 + lane]      = h[n * 64 + lane];
            out[n * 64 + lane + 32] = h[n * 64 + lane + 32];
        }
    }
}

// ---------------------------------------------------------------------------
extern "C" void kernel_launch(void* const* d_in, const int* in_sizes, int n_in,
                              void* d_out, int out_size)
{
    const float* h  = (const float*)d_in[0];
    const float* nf = (const float*)d_in[1];
    const float* ef = (const float*)d_in[2];
    const int*  src = (const int*)d_in[3];
    const int*  dst = (const int*)d_in[4];
    const float* W1 = (const float*)d_in[5];
    const float* W2 = (const float*)d_in[6];
    float* out = (float*)d_out;

    int N = in_sizes[1] / 32;   // nf is [N, 32]
    int E = in_sizes[3];        // src is [E]

    int grid1 = (N + 31) / 32;             // 4 groups/block * 8 nodes/group
    int grid2 = (E * 21 + 255) / 256;      // thread per (edge, chunk)
    int grid3 = (N + 31) / 32;             // 8 warps/block * 4 nodes/warp

    precompute_kernel<<<grid1, 256>>>(h, nf, W1, N);
    edge_kernel<<<grid2, 256>>>(src, dst, ef, E);
    finalize_kernel<<<grid3, 256>>>(h, W1, W2, out, N);
}

// round 5
// speedup vs baseline: 1.4034x; 1.2664x over previous
#include <cuda_runtime.h>

#define NN 50000
#define HH 64
#define MAILW 84   // 64 u-sum + 16 ef-sum + 1 deg + 3 pad  (21 float4)

// Scratch (no runtime allocation allowed)
__device__ __align__(16) float g_u[NN * HH];      // h @ W1d^T
__device__ __align__(16) float g_p[NN * HH];      // nf @ W1a^T
__device__ __align__(16) float g_q[NN * HH];      // nf @ W1b^T
__device__ __align__(16) float g_mail[NN * MAILW];

// Pre-transposed weights (filled by prep_kernel)
__device__ __align__(16) float g_WpqT[32 * 128];  // [k][j]: j<64 -> W1a, j>=64 -> W1b
__device__ __align__(16) float g_WuT[64 * 64];    // [k][j] = W1[j][80+k]
__device__ __align__(16) float g_W1cT[16 * 64];   // [k][j] = W1[j][64+k]
__device__ __align__(16) float g_W2T[64 * 64];    // [j][i] = W2[i][j]

__device__ __forceinline__ void fma4(float4& a, float x, const float4& wv) {
    a.x = fmaf(x, wv.x, a.x);
    a.y = fmaf(x, wv.y, a.y);
    a.z = fmaf(x, wv.z, a.z);
    a.w = fmaf(x, wv.w, a.w);
}

// ---------------------------------------------------------------------------
// Kernel 0: block 0 transposes weights into global scratch; all blocks zero
// the mailbox.
// ---------------------------------------------------------------------------
__global__ __launch_bounds__(256) void prep_kernel(
    const float* __restrict__ W1, const float* __restrict__ W2)
{
    // zero mailbox (grid-stride float4 stores)
    float4* m4 = reinterpret_cast<float4*>(g_mail);
    int total = NN * (MAILW / 4);
    float4 z = make_float4(0.f, 0.f, 0.f, 0.f);
    for (int i = blockIdx.x * blockDim.x + threadIdx.x; i < total;
         i += gridDim.x * blockDim.x)
        m4[i] = z;

    if (blockIdx.x == 0) {
        for (int idx = threadIdx.x; idx < 64 * 144; idx += 256) {
            int j = idx / 144, k = idx % 144;
            float w = W1[idx];
            if (k < 32)       g_WpqT[k * 128 + j] = w;
            else if (k < 64)  g_WpqT[(k - 32) * 128 + 64 + j] = w;
            else if (k < 80)  g_W1cT[(k - 64) * 64 + j] = w;
            else              g_WuT[(k - 80) * 64 + j] = w;
        }
        for (int idx = threadIdx.x; idx < 64 * 64; idx += 256) {
            int i = idx >> 6, j = idx & 63;
            g_W2T[j * 64 + i] = W2[idx];
        }
    }
}

// ---------------------------------------------------------------------------
// Kernel 1a: [p|q] = nf @ [W1a^T | W1b^T].  Tile: 64 nodes x 128 outputs, K=32.
// Thread: jg = tid&31 (4 outputs), ng = tid>>5 (8 nodes). Per k: 1 LDS.128
// weight + 8 broadcast x reads -> 32 FMA.
// ---------------------------------------------------------------------------
__global__ __launch_bounds__(256) void pq_kernel(const float* __restrict__ nf, int N)
{
    __shared__ float sW[32 * 128];  // [k][j]
    __shared__ float sX[64 * 32];   // [node][k]

    for (int idx = threadIdx.x; idx < 32 * 128; idx += 256)
        sW[idx] = g_WpqT[idx];

    int n0 = blockIdx.x * 64;
    const float4* nf4 = reinterpret_cast<const float4*>(nf);
    float4* sX4 = reinterpret_cast<float4*>(sX);
    for (int idx = threadIdx.x; idx < 512; idx += 256) {
        int n = n0 + (idx >> 3);
        sX4[idx] = (n < N) ? __ldg(&nf4[n * 8 + (idx & 7)])
                           : make_float4(0.f, 0.f, 0.f, 0.f);
    }
    __syncthreads();

    int jg = threadIdx.x & 31;
    int ng = threadIdx.x >> 5;
    const float* xb = sX + ng * 8 * 32;
    const float4* sW4 = reinterpret_cast<const float4*>(sW);

    float4 acc[8];
    #pragma unroll
    for (int i = 0; i < 8; i++) acc[i] = make_float4(0.f, 0.f, 0.f, 0.f);

    #pragma unroll 8
    for (int k = 0; k < 32; k++) {
        float4 wv = sW4[k * 32 + jg];
        #pragma unroll
        for (int i = 0; i < 8; i++) {
            fma4(acc[i], xb[i * 32 + k], wv);
        }
    }

    float4* dst4 = (jg < 16) ? reinterpret_cast<float4*>(g_p)
                             : reinterpret_cast<float4*>(g_q);
    int jj = jg & 15;
    #pragma unroll
    for (int i = 0; i < 8; i++) {
        int n = n0 + ng * 8 + i;
        if (n < N) dst4[n * 16 + jj] = acc[i];
    }
}

// ---------------------------------------------------------------------------
// Kernel 1b: u = h @ W1d^T.  Tile: 128 nodes x 64 outputs, K=64.
// Thread: jg = tid&15 (4 outputs), ng = tid>>4 (8 nodes).
// ---------------------------------------------------------------------------
__global__ __launch_bounds__(256) void u_kernel(const float* __restrict__ h, int N)
{
    __shared__ float sW[64 * 64];   // [k][j]  16KB
    __shared__ float sX[128 * 64];  // [node][k]  32KB

    for (int idx = threadIdx.x; idx < 64 * 64; idx += 256)
        sW[idx] = g_WuT[idx];

    int n0 = blockIdx.x * 128;
    const float4* h4 = reinterpret_cast<const float4*>(h);
    float4* sX4 = reinterpret_cast<float4*>(sX);
    for (int idx = threadIdx.x; idx < 2048; idx += 256) {
        int n = n0 + (idx >> 4);
        sX4[idx] = (n < N) ? __ldg(&h4[n * 16 + (idx & 15)])
                           : make_float4(0.f, 0.f, 0.f, 0.f);
    }
    __syncthreads();

    int jg = threadIdx.x & 15;
    int ng = threadIdx.x >> 4;
    const float* xb = sX + ng * 8 * 64;
    const float4* sW4 = reinterpret_cast<const float4*>(sW);

    float4 acc[8];
    #pragma unroll
    for (int i = 0; i < 8; i++) acc[i] = make_float4(0.f, 0.f, 0.f, 0.f);

    #pragma unroll 8
    for (int k = 0; k < 64; k++) {
        float4 wv = sW4[k * 16 + jg];
        #pragma unroll
        for (int i = 0; i < 8; i++) {
            fma4(acc[i], xb[i * 64 + k], wv);
        }
    }

    float4* du4 = reinterpret_cast<float4*>(g_u);
    #pragma unroll
    for (int i = 0; i < 8; i++) {
        int n = n0 + ng * 8 + i;
        if (n < N) du4[n * 16 + jg] = acc[i];
    }
}

// ---------------------------------------------------------------------------
// Kernel 2: thread per (edge, float4-chunk). Scatters [u[src] (16 chunks),
// ef[e] (4 chunks), deg (1 chunk)] into mailbox[dst] via vector RED.
// ---------------------------------------------------------------------------
__global__ __launch_bounds__(256) void edge_kernel(
    const int* __restrict__ src, const int* __restrict__ dst,
    const float* __restrict__ ef, int E)
{
    int gid = blockIdx.x * blockDim.x + threadIdx.x;
    int total = E * 21;
    if (gid >= total) return;

    int e = gid / 21;
    int c = gid - e * 21;

    int s = __ldg(&src[e]);
    int d = __ldg(&dst[e]);

    const float4* u4  = reinterpret_cast<const float4*>(g_u);
    const float4* ef4 = reinterpret_cast<const float4*>(ef);
    float4* mail4 = reinterpret_cast<float4*>(g_mail);

    float4 v;
    if (c < 16)      v = __ldg(&u4[s * 16 + c]);
    else if (c < 20) v = __ldg(&ef4[e * 4 + (c - 16)]);
    else             v = make_float4(1.f, 0.f, 0.f, 0.f);
    atomicAdd(&mail4[d * 21 + c], v);
}

// ---------------------------------------------------------------------------
// Kernel 3: warp per 4 nodes, register-blocked W2 GEMM with smem y staging.
// y = mail_u + p + deg*q + W1c@mail_ef; relu; out = (deg>0) ? y@W2^T : h
// ---------------------------------------------------------------------------
__global__ __launch_bounds__(256) void finalize_kernel(
    const float* __restrict__ h, float* __restrict__ out, int N)
{
    __shared__ float sW1cT[16 * 64];   // [k][j]
    __shared__ float sW2T[64 * 64];    // [j][i]
    __shared__ float sY[8][4 * 64];    // per-warp staging: 4 nodes x 64

    for (int idx = threadIdx.x; idx < 16 * 64; idx += 256) sW1cT[idx] = g_W1cT[idx];
    for (int idx = threadIdx.x; idx < 64 * 64; idx += 256) sW2T[idx]  = g_W2T[idx];
    __syncthreads();

    int lane = threadIdx.x & 31;
    int warp = threadIdx.x >> 5;
    int gw = (blockIdx.x * blockDim.x + threadIdx.x) >> 5;
    int nb = gw * 4;
    if (nb >= N) return;
    int cnt = min(4, N - nb);

    float dgv[4];

    for (int m = 0; m < cnt; m++) {
        int n = nb + m;
        const float* mail = g_mail + n * MAILW;
        float dg = __ldg(&mail[80]);
        dgv[m] = dg;

        float y0 = mail[lane]      + g_p[n * 64 + lane]      + dg * g_q[n * 64 + lane];
        float y1 = mail[lane + 32] + g_p[n * 64 + lane + 32] + dg * g_q[n * 64 + lane + 32];

        #pragma unroll
        for (int k = 0; k < 16; k++) {
            float mk = __ldg(&mail[64 + k]);
            y0 = fmaf(mk, sW1cT[k * 64 + lane],      y0);
            y1 = fmaf(mk, sW1cT[k * 64 + lane + 32], y1);
        }
        sY[warp][m * 64 + lane]      = fmaxf(y0, 0.f);
        sY[warp][m * 64 + lane + 32] = fmaxf(y1, 0.f);
    }
    __syncwarp();

    float o0[4] = {0.f, 0.f, 0.f, 0.f};
    float o1[4] = {0.f, 0.f, 0.f, 0.f};
    #pragma unroll
    for (int j = 0; j < 64; j++) {
        float w0 = sW2T[j * 64 + lane];
        float w1 = sW2T[j * 64 + lane + 32];
        #pragma unroll
        for (int m = 0; m < 4; m++) {
            float yj = sY[warp][m * 64 + j];
            o0[m] = fmaf(yj, w0, o0[m]);
            o1[m] = fmaf(yj, w1, o1[m]);
        }
    }

    for (int m = 0; m < cnt; m++) {
        int n = nb + m;
        if (dgv[m] > 0.f) {
            out[n * 64 + lane]      = o0[m];
            out[n * 64 + lane + 32] = o1[m];
        } else {
            out[n * 64 + lane]      = h[n * 64 + lane];
            out[n * 64 + lane + 32] = h[n * 64 + lane + 32];
        }
    }
}

// ---------------------------------------------------------------------------
extern "C" void kernel_launch(void* const* d_in, const int* in_sizes, int n_in,
                              void* d_out, int out_size)
{
    const float* h  = (const float*)d_in[0];
    const float* nf = (const float*)d_in[1];
    const float* ef = (const float*)d_in[2];
    const int*  src = (const int*)d_in[3];
    const int*  dst = (const int*)d_in[4];
    const float* W1 = (const float*)d_in[5];
    const float* W2 = (const float*)d_in[6];
    float* out = (float*)d_out;

    int N = in_sizes[1] / 32;   // nf is [N, 32]
    int E = in_sizes[3];        // src is [E]

    int gpq = (N + 63) / 64;
    int gu  = (N + 127) / 128;
    int ge  = (E * 21 + 255) / 256;
    int gf  = (N + 31) / 32;

    prep_kernel<<<148, 256>>>(W1, W2);
    pq_kernel<<<gpq, 256>>>(nf, N);
    u_kernel<<<gu, 256>>>(h, N);
    edge_kernel<<<ge, 256>>>(src, dst, ef, E);
    finalize_kernel<<<gf, 256>>>(h, out, N);
}

// round 6
// speedup vs baseline: 1.4686x; 1.0464x over previous
#include <cuda_runtime.h>

#define NN 50000
#define NE 800000
#define HH 64

// Scratch (no runtime allocation allowed)
__device__ __align__(16) float g_u[NN * HH];      // h @ W1d^T
__device__ __align__(16) float g_p[NN * HH];      // nf @ W1a^T
__device__ __align__(16) float g_q[NN * HH];      // nf @ W1b^T

// CSR build scratch
__device__ int  g_cnt[NN];
__device__ int  g_off[NN + 1];
__device__ int  g_cur[NN];
__device__ int  g_bsum[64];
__device__ __align__(8) int2 g_edge[NE];          // (src, edge_idx) sorted by dst

// Pre-transposed weights (filled by prep_kernel)
__device__ __align__(16) float g_WpqT[32 * 128];  // [k][j]: j<64 -> W1a, j>=64 -> W1b
__device__ __align__(16) float g_WuT[64 * 64];    // [k][j] = W1[j][80+k]
__device__ __align__(16) float g_W1cT[16 * 64];   // [k][j] = W1[j][64+k]
__device__ __align__(16) float g_W2T[64 * 64];    // [j][i] = W2[i][j]

__device__ __forceinline__ void fma4(float4& a, float x, const float4& wv) {
    a.x = fmaf(x, wv.x, a.x);
    a.y = fmaf(x, wv.y, a.y);
    a.z = fmaf(x, wv.z, a.z);
    a.w = fmaf(x, wv.w, a.w);
}

// ---------------------------------------------------------------------------
// Kernel 0: zero degree counters; block 0 transposes weights.
// ---------------------------------------------------------------------------
__global__ __launch_bounds__(256) void prep_kernel(
    const float* __restrict__ W1, const float* __restrict__ W2)
{
    int tid = blockIdx.x * blockDim.x + threadIdx.x;
    for (int i = tid; i < NN; i += gridDim.x * blockDim.x) g_cnt[i] = 0;

    if (blockIdx.x == 0) {
        for (int idx = threadIdx.x; idx < 64 * 144; idx += 256) {
            int j = idx / 144, k = idx % 144;
            float w = W1[idx];
            if (k < 32)       g_WpqT[k * 128 + j] = w;
            else if (k < 64)  g_WpqT[(k - 32) * 128 + 64 + j] = w;
            else if (k < 80)  g_W1cT[(k - 64) * 64 + j] = w;
            else              g_WuT[(k - 80) * 64 + j] = w;
        }
        for (int idx = threadIdx.x; idx < 64 * 64; idx += 256) {
            int i = idx >> 6, j = idx & 63;
            g_W2T[j * 64 + i] = W2[idx];
        }
    }
}

// ---------------------------------------------------------------------------
// CSR build: histogram of dst
// ---------------------------------------------------------------------------
__global__ __launch_bounds__(256) void hist_kernel(const int* __restrict__ dst, int E)
{
    int i = blockIdx.x * blockDim.x + threadIdx.x;
    if (i < E) atomicAdd(&g_cnt[__ldg(&dst[i])], 1);
}

// ---------------------------------------------------------------------------
// CSR build: per-1024-chunk exclusive scan (Hillis-Steele) + chunk totals
// ---------------------------------------------------------------------------
__global__ __launch_bounds__(1024) void scan1_kernel()
{
    __shared__ int s[1024];
    int tid = threadIdx.x;
    int idx = blockIdx.x * 1024 + tid;
    int v = (idx < NN) ? g_cnt[idx] : 0;
    s[tid] = v;
    __syncthreads();
    #pragma unroll
    for (int d = 1; d < 1024; d <<= 1) {
        int t = (tid >= d) ? s[tid - d] : 0;
        __syncthreads();
        s[tid] += t;
        __syncthreads();
    }
    if (idx < NN) g_off[idx] = s[tid] - v;   // exclusive
    if (tid == 1023) g_bsum[blockIdx.x] = s[1023];
}

// ---------------------------------------------------------------------------
// CSR build: add chunk-prefix; copy to g_cur for the scatter pass
// ---------------------------------------------------------------------------
__global__ __launch_bounds__(1024) void scan2_kernel(int E)
{
    int b = blockIdx.x, tid = threadIdx.x;
    int idx = b * 1024 + tid;
    int add = 0;
    for (int j = 0; j < b; j++) add += g_bsum[j];   // uniform, tiny
    if (idx < NN) {
        int v = g_off[idx] + add;
        g_off[idx] = v;
        g_cur[idx] = v;
    }
    if (b == 0 && tid == 0) g_off[NN] = E;
}

// ---------------------------------------------------------------------------
// CSR build: scatter (src, edge_idx) into dst-sorted slots
// ---------------------------------------------------------------------------
__global__ __launch_bounds__(256) void scatter_kernel(
    const int* __restrict__ src, const int* __restrict__ dst, int E)
{
    int i = blockIdx.x * blockDim.x + threadIdx.x;
    if (i >= E) return;
    int d = __ldg(&dst[i]);
    int pos = atomicAdd(&g_cur[d], 1);
    g_edge[pos] = make_int2(__ldg(&src[i]), i);
}

// ---------------------------------------------------------------------------
// Kernel 1a: [p|q] = nf @ [W1a^T | W1b^T].  Tile: 64 nodes x 128 outputs, K=32.
// ---------------------------------------------------------------------------
__global__ __launch_bounds__(256) void pq_kernel(const float* __restrict__ nf, int N)
{
    __shared__ float sW[32 * 128];  // [k][j]
    __shared__ float sX[64 * 32];   // [node][k]

    for (int idx = threadIdx.x; idx < 32 * 128; idx += 256)
        sW[idx] = g_WpqT[idx];

    int n0 = blockIdx.x * 64;
    const float4* nf4 = reinterpret_cast<const float4*>(nf);
    float4* sX4 = reinterpret_cast<float4*>(sX);
    for (int idx = threadIdx.x; idx < 512; idx += 256) {
        int n = n0 + (idx >> 3);
        sX4[idx] = (n < N) ? __ldg(&nf4[n * 8 + (idx & 7)])
                           : make_float4(0.f, 0.f, 0.f, 0.f);
    }
    __syncthreads();

    int jg = threadIdx.x & 31;
    int ng = threadIdx.x >> 5;
    const float* xb = sX + ng * 8 * 32;
    const float4* sW4 = reinterpret_cast<const float4*>(sW);

    float4 acc[8];
    #pragma unroll
    for (int i = 0; i < 8; i++) acc[i] = make_float4(0.f, 0.f, 0.f, 0.f);

    #pragma unroll 8
    for (int k = 0; k < 32; k++) {
        float4 wv = sW4[k * 32 + jg];
        #pragma unroll
        for (int i = 0; i < 8; i++) fma4(acc[i], xb[i * 32 + k], wv);
    }

    float4* dst4 = (jg < 16) ? reinterpret_cast<float4*>(g_p)
                             : reinterpret_cast<float4*>(g_q);
    int jj = jg & 15;
    #pragma unroll
    for (int i = 0; i < 8; i++) {
        int n = n0 + ng * 8 + i;
        if (n < N) dst4[n * 16 + jj] = acc[i];
    }
}

// ---------------------------------------------------------------------------
// Kernel 1b: u = h @ W1d^T.  Tile: 128 nodes x 64 outputs, K=64.
// ---------------------------------------------------------------------------
__global__ __launch_bounds__(256) void u_kernel(const float* __restrict__ h, int N)
{
    __shared__ float sW[64 * 64];   // [k][j]
    __shared__ float sX[128 * 64];  // [node][k]

    for (int idx = threadIdx.x; idx < 64 * 64; idx += 256)
        sW[idx] = g_WuT[idx];

    int n0 = blockIdx.x * 128;
    const float4* h4 = reinterpret_cast<const float4*>(h);
    float4* sX4 = reinterpret_cast<float4*>(sX);
    for (int idx = threadIdx.x; idx < 2048; idx += 256) {
        int n = n0 + (idx >> 4);
        sX4[idx] = (n < N) ? __ldg(&h4[n * 16 + (idx & 15)])
                           : make_float4(0.f, 0.f, 0.f, 0.f);
    }
    __syncthreads();

    int jg = threadIdx.x & 15;
    int ng = threadIdx.x >> 4;
    const float* xb = sX + ng * 8 * 64;
    const float4* sW4 = reinterpret_cast<const float4*>(sW);

    float4 acc[8];
    #pragma unroll
    for (int i = 0; i < 8; i++) acc[i] = make_float4(0.f, 0.f, 0.f, 0.f);

    #pragma unroll 8
    for (int k = 0; k < 64; k++) {
        float4 wv = sW4[k * 16 + jg];
        #pragma unroll
        for (int i = 0; i < 8; i++) fma4(acc[i], xb[i * 64 + k], wv);
    }

    float4* du4 = reinterpret_cast<float4*>(g_u);
    #pragma unroll
    for (int i = 0; i < 8; i++) {
        int n = n0 + ng * 8 + i;
        if (n < N) du4[n * 16 + jg] = acc[i];
    }
}

// ---------------------------------------------------------------------------
// Fused gather + finalize. Warp handles 4 nodes:
//   phase 1 (per node): walk CSR slice, accumulate [sum u[src] | sum ef | deg]
//                       in registers, compute y, relu, stage in smem.
//   phase 2: 4-node register-blocked W2 GEMM; out = (deg>0) ? y@W2^T : h.
// No atomics, no mailbox.
// ---------------------------------------------------------------------------
__global__ __launch_bounds__(256) void gather_finalize_kernel(
    const float* __restrict__ h, const float* __restrict__ ef,
    float* __restrict__ out, int N)
{
    __shared__ float sW1cT[16 * 64];
    __shared__ float sW2T[64 * 64];
    __shared__ float sY[8][4 * 64];

    for (int idx = threadIdx.x; idx < 16 * 64; idx += 256) sW1cT[idx] = g_W1cT[idx];
    for (int idx = threadIdx.x; idx < 64 * 64; idx += 256) sW2T[idx]  = g_W2T[idx];
    __syncthreads();

    int lane = threadIdx.x & 31;
    int warp = threadIdx.x >> 5;
    int gw = (blockIdx.x * blockDim.x + threadIdx.x) >> 5;
    int nb = gw * 4;
    if (nb >= N) return;
    int cnt = min(4, N - nb);

    float dgv[4];

    for (int m = 0; m < cnt; m++) {
        int n = nb + m;
        int off0 = __ldg(&g_off[n]);
        int off1 = __ldg(&g_off[n + 1]);
        dgv[m] = (float)(off1 - off0);

        float a0 = 0.f, a1 = 0.f, aef = 0.f;
        for (int i = off0; i < off1; i++) {
            int2 se = g_edge[i];                       // uniform broadcast load
            a0 += __ldg(&g_u[se.x * 64 + lane]);
            a1 += __ldg(&g_u[se.x * 64 + lane + 32]);
            if (lane < 16) aef += __ldg(&ef[se.y * 16 + lane]);
        }

        float dg = dgv[m];
        float y0 = a0 + g_p[n * 64 + lane]      + dg * g_q[n * 64 + lane];
        float y1 = a1 + g_p[n * 64 + lane + 32] + dg * g_q[n * 64 + lane + 32];

        #pragma unroll
        for (int k = 0; k < 16; k++) {
            float mk = __shfl_sync(0xffffffffu, aef, k);
            y0 = fmaf(mk, sW1cT[k * 64 + lane],      y0);
            y1 = fmaf(mk, sW1cT[k * 64 + lane + 32], y1);
        }
        sY[warp][m * 64 + lane]      = fmaxf(y0, 0.f);
        sY[warp][m * 64 + lane + 32] = fmaxf(y1, 0.f);
    }
    __syncwarp();

    float o0[4] = {0.f, 0.f, 0.f, 0.f};
    float o1[4] = {0.f, 0.f, 0.f, 0.f};
    #pragma unroll
    for (int j = 0; j < 64; j++) {
        float w0 = sW2T[j * 64 + lane];
        float w1 = sW2T[j * 64 + lane + 32];
        #pragma unroll
        for (int m = 0; m < 4; m++) {
            float yj = sY[warp][m * 64 + j];
            o0[m] = fmaf(yj, w0, o0[m]);
            o1[m] = fmaf(yj, w1, o1[m]);
        }
    }

    for (int m = 0; m < cnt; m++) {
        int n = nb + m;
        if (dgv[m] > 0.f) {
            out[n * 64 + lane]      = o0[m];
            out[n * 64 + lane + 32] = o1[m];
        } else {
            out[n * 64 + lane]      = h[n * 64 + lane];
            out[n * 64 + lane + 32] = h[n * 64 + lane + 32];
        }
    }
}

// ---------------------------------------------------------------------------
extern "C" void kernel_launch(void* const* d_in, const int* in_sizes, int n_in,
                              void* d_out, int out_size)
{
    const float* h  = (const float*)d_in[0];
    const float* nf = (const float*)d_in[1];
    const float* ef = (const float*)d_in[2];
    const int*  src = (const int*)d_in[3];
    const int*  dst = (const int*)d_in[4];
    const float* W1 = (const float*)d_in[5];
    const float* W2 = (const float*)d_in[6];
    float* out = (float*)d_out;

    int N = in_sizes[1] / 32;   // nf is [N, 32]
    int E = in_sizes[3];        // src is [E]

    int ge   = (E + 255) / 256;
    int gsc  = (NN + 1023) / 1024;   // 49
    int gpq  = (N + 63) / 64;
    int gu   = (N + 127) / 128;
    int gf   = (N + 31) / 32;

    prep_kernel<<<148, 256>>>(W1, W2);
    hist_kernel<<<ge, 256>>>(dst, E);
    scan1_kernel<<<gsc, 1024>>>();
    scan2_kernel<<<gsc, 1024>>>(E);
    scatter_kernel<<<ge, 256>>>(src, dst, E);
    pq_kernel<<<gpq, 256>>>(nf, N);
    u_kernel<<<gu, 256>>>(h, N);
    gather_finalize_kernel<<<gf, 256>>>(h, ef, out, N);
}

// round 7
// speedup vs baseline: 1.6529x; 1.1255x over previous
#include <cuda_runtime.h>

#define NN 50000
#define NE 800000
#define HH 64

// Scratch (no runtime allocation allowed)
__device__ __align__(16) float g_u[NN * HH];      // h @ W1d^T
__device__ __align__(16) float g_p[NN * HH];      // nf @ W1a^T
__device__ __align__(16) float g_q[NN * HH];      // nf @ W1b^T

// CSR build scratch
__device__ int  g_cnt[NN];
__device__ int  g_off[NN + 1];
__device__ int  g_cur[NN];
__device__ int  g_bsum[64];
__device__ __align__(16) int2 g_edge[NE];         // (src, edge_idx) sorted by dst

// Pre-transposed weights (filled by prep_kernel)
__device__ __align__(16) float g_WpqT[32 * 128];  // [k][j]: j<64 -> W1a, j>=64 -> W1b
__device__ __align__(16) float g_WuT[64 * 64];    // [k][j] = W1[j][80+k]
__device__ __align__(16) float g_W1cT[16 * 64];   // [k][j] = W1[j][64+k]
__device__ __align__(16) float g_W2T[64 * 64];    // [j][i] = W2[i][j]

__device__ __forceinline__ void fma4(float4& a, float x, const float4& wv) {
    a.x = fmaf(x, wv.x, a.x);
    a.y = fmaf(x, wv.y, a.y);
    a.z = fmaf(x, wv.z, a.z);
    a.w = fmaf(x, wv.w, a.w);
}

// ---------------------------------------------------------------------------
// Kernel 0: zero degree counters; block 0 transposes weights.
// ---------------------------------------------------------------------------
__global__ __launch_bounds__(256) void prep_kernel(
    const float* __restrict__ W1, const float* __restrict__ W2)
{
    int tid = blockIdx.x * blockDim.x + threadIdx.x;
    for (int i = tid; i < NN; i += gridDim.x * blockDim.x) g_cnt[i] = 0;

    if (blockIdx.x == 0) {
        for (int idx = threadIdx.x; idx < 64 * 144; idx += 256) {
            int j = idx / 144, k = idx % 144;
            float w = W1[idx];
            if (k < 32)       g_WpqT[k * 128 + j] = w;
            else if (k < 64)  g_WpqT[(k - 32) * 128 + 64 + j] = w;
            else if (k < 80)  g_W1cT[(k - 64) * 64 + j] = w;
            else              g_WuT[(k - 80) * 64 + j] = w;
        }
        for (int idx = threadIdx.x; idx < 64 * 64; idx += 256) {
            int i = idx >> 6, j = idx & 63;
            g_W2T[j * 64 + i] = W2[idx];
        }
    }
}

// ---------------------------------------------------------------------------
// CSR build: histogram of dst
// ---------------------------------------------------------------------------
__global__ __launch_bounds__(256) void hist_kernel(const int* __restrict__ dst, int E)
{
    int i = blockIdx.x * blockDim.x + threadIdx.x;
    if (i < E) atomicAdd(&g_cnt[__ldg(&dst[i])], 1);
}

// ---------------------------------------------------------------------------
// CSR build: per-1024-chunk exclusive scan (Hillis-Steele) + chunk totals
// ---------------------------------------------------------------------------
__global__ __launch_bounds__(1024) void scan1_kernel()
{
    __shared__ int s[1024];
    int tid = threadIdx.x;
    int idx = blockIdx.x * 1024 + tid;
    int v = (idx < NN) ? g_cnt[idx] : 0;
    s[tid] = v;
    __syncthreads();
    #pragma unroll
    for (int d = 1; d < 1024; d <<= 1) {
        int t = (tid >= d) ? s[tid - d] : 0;
        __syncthreads();
        s[tid] += t;
        __syncthreads();
    }
    if (idx < NN) g_off[idx] = s[tid] - v;   // exclusive
    if (tid == 1023) g_bsum[blockIdx.x] = s[1023];
}

// ---------------------------------------------------------------------------
// CSR build: add chunk-prefix; copy to g_cur for the scatter pass
// ---------------------------------------------------------------------------
__global__ __launch_bounds__(1024) void scan2_kernel(int E)
{
    int b = blockIdx.x, tid = threadIdx.x;
    int idx = b * 1024 + tid;
    int add = 0;
    for (int j = 0; j < b; j++) add += g_bsum[j];   // uniform, tiny
    if (idx < NN) {
        int v = g_off[idx] + add;
        g_off[idx] = v;
        g_cur[idx] = v;
    }
    if (b == 0 && tid == 0) g_off[NN] = E;
}

// ---------------------------------------------------------------------------
// CSR build: scatter (src, edge_idx) into dst-sorted slots
// ---------------------------------------------------------------------------
__global__ __launch_bounds__(256) void scatter_kernel(
    const int* __restrict__ src, const int* __restrict__ dst, int E)
{
    int i = blockIdx.x * blockDim.x + threadIdx.x;
    if (i >= E) return;
    int d = __ldg(&dst[i]);
    int pos = atomicAdd(&g_cur[d], 1);
    g_edge[pos] = make_int2(__ldg(&src[i]), i);
}

// ---------------------------------------------------------------------------
// Kernel 1a: [p|q] = nf @ [W1a^T | W1b^T].  Tile: 64 nodes x 128 outputs, K=32.
// ---------------------------------------------------------------------------
__global__ __launch_bounds__(256) void pq_kernel(const float* __restrict__ nf, int N)
{
    __shared__ float sW[32 * 128];  // [k][j]
    __shared__ float sX[64 * 32];   // [node][k]

    for (int idx = threadIdx.x; idx < 32 * 128; idx += 256)
        sW[idx] = g_WpqT[idx];

    int n0 = blockIdx.x * 64;
    const float4* nf4 = reinterpret_cast<const float4*>(nf);
    float4* sX4 = reinterpret_cast<float4*>(sX);
    for (int idx = threadIdx.x; idx < 512; idx += 256) {
        int n = n0 + (idx >> 3);
        sX4[idx] = (n < N) ? __ldg(&nf4[n * 8 + (idx & 7)])
                           : make_float4(0.f, 0.f, 0.f, 0.f);
    }
    __syncthreads();

    int jg = threadIdx.x & 31;
    int ng = threadIdx.x >> 5;
    const float* xb = sX + ng * 8 * 32;
    const float4* sW4 = reinterpret_cast<const float4*>(sW);

    float4 acc[8];
    #pragma unroll
    for (int i = 0; i < 8; i++) acc[i] = make_float4(0.f, 0.f, 0.f, 0.f);

    #pragma unroll 8
    for (int k = 0; k < 32; k++) {
        float4 wv = sW4[k * 32 + jg];
        #pragma unroll
        for (int i = 0; i < 8; i++) fma4(acc[i], xb[i * 32 + k], wv);
    }

    float4* dst4 = (jg < 16) ? reinterpret_cast<float4*>(g_p)
                             : reinterpret_cast<float4*>(g_q);
    int jj = jg & 15;
    #pragma unroll
    for (int i = 0; i < 8; i++) {
        int n = n0 + ng * 8 + i;
        if (n < N) dst4[n * 16 + jj] = acc[i];
    }
}

// ---------------------------------------------------------------------------
// Kernel 1b: u = h @ W1d^T.  Tile: 128 nodes x 64 outputs, K=64.
// ---------------------------------------------------------------------------
__global__ __launch_bounds__(256) void u_kernel(const float* __restrict__ h, int N)
{
    __shared__ float sW[64 * 64];   // [k][j]
    __shared__ float sX[128 * 64];  // [node][k]

    for (int idx = threadIdx.x; idx < 64 * 64; idx += 256)
        sW[idx] = g_WuT[idx];

    int n0 = blockIdx.x * 128;
    const float4* h4 = reinterpret_cast<const float4*>(h);
    float4* sX4 = reinterpret_cast<float4*>(sX);
    for (int idx = threadIdx.x; idx < 2048; idx += 256) {
        int n = n0 + (idx >> 4);
        sX4[idx] = (n < N) ? __ldg(&h4[n * 16 + (idx & 15)])
                           : make_float4(0.f, 0.f, 0.f, 0.f);
    }
    __syncthreads();

    int jg = threadIdx.x & 15;
    int ng = threadIdx.x >> 4;
    const float* xb = sX + ng * 8 * 64;
    const float4* sW4 = reinterpret_cast<const float4*>(sW);

    float4 acc[8];
    #pragma unroll
    for (int i = 0; i < 8; i++) acc[i] = make_float4(0.f, 0.f, 0.f, 0.f);

    #pragma unroll 8
    for (int k = 0; k < 64; k++) {
        float4 wv = sW4[k * 16 + jg];
        #pragma unroll
        for (int i = 0; i < 8; i++) fma4(acc[i], xb[i * 64 + k], wv);
    }

    float4* du4 = reinterpret_cast<float4*>(g_u);
    #pragma unroll
    for (int i = 0; i < 8; i++) {
        int n = n0 + ng * 8 + i;
        if (n < N) du4[n * 16 + jg] = acc[i];
    }
}

// ---------------------------------------------------------------------------
// Fused gather + finalize, 4-edge unrolled for MLP.
// Warp handles 4 nodes: walk CSR slice accumulating [sum u[src] | sum ef | deg]
// with 8-12 loads in flight, then y = sums + p + deg*q + W1c@ef_sum, relu,
// staged 4-node W2 GEMM. No atomics, no mailbox.
// ---------------------------------------------------------------------------
__global__ __launch_bounds__(256) void gather_finalize_kernel(
    const float* __restrict__ h, const float* __restrict__ ef,
    float* __restrict__ out, int N)
{
    __shared__ float sW1cT[16 * 64];
    __shared__ float sW2T[64 * 64];
    __shared__ float sY[8][4 * 64];

    for (int idx = threadIdx.x; idx < 16 * 64; idx += 256) sW1cT[idx] = g_W1cT[idx];
    for (int idx = threadIdx.x; idx < 64 * 64; idx += 256) sW2T[idx]  = g_W2T[idx];
    __syncthreads();

    int lane = threadIdx.x & 31;
    int warp = threadIdx.x >> 5;
    int gw = (blockIdx.x * blockDim.x + threadIdx.x) >> 5;
    int nb = gw * 4;
    if (nb >= N) return;
    int cnt = min(4, N - nb);

    float dgv[4];

    for (int m = 0; m < cnt; m++) {
        int n = nb + m;
        int off0 = __ldg(&g_off[n]);
        int off1 = __ldg(&g_off[n + 1]);
        dgv[m] = (float)(off1 - off0);

        float a0 = 0.f, a1 = 0.f, b0 = 0.f, b1 = 0.f;
        float aef = 0.f, bef = 0.f;

        int i = off0;
        for (; i + 4 <= off1; i += 4) {
            // hoist all index loads, then fire 8 u-gathers + 4 ef-loads together
            int2 e0 = g_edge[i];
            int2 e1 = g_edge[i + 1];
            int2 e2 = g_edge[i + 2];
            int2 e3 = g_edge[i + 3];
            const float* u0 = g_u + e0.x * 64 + lane;
            const float* u1 = g_u + e1.x * 64 + lane;
            const float* u2 = g_u + e2.x * 64 + lane;
            const float* u3 = g_u + e3.x * 64 + lane;
            float v00 = __ldg(u0),      v01 = __ldg(u0 + 32);
            float v10 = __ldg(u1),      v11 = __ldg(u1 + 32);
            float v20 = __ldg(u2),      v21 = __ldg(u2 + 32);
            float v30 = __ldg(u3),      v31 = __ldg(u3 + 32);
            float f0 = 0.f, f1 = 0.f, f2 = 0.f, f3 = 0.f;
            if (lane < 16) {
                f0 = __ldg(&ef[e0.y * 16 + lane]);
                f1 = __ldg(&ef[e1.y * 16 + lane]);
                f2 = __ldg(&ef[e2.y * 16 + lane]);
                f3 = __ldg(&ef[e3.y * 16 + lane]);
            }
            a0 += v00; a1 += v01;
            b0 += v10; b1 += v11;
            a0 += v20; a1 += v21;
            b0 += v30; b1 += v31;
            aef += f0; bef += f1;
            aef += f2; bef += f3;
        }
        for (; i < off1; i++) {
            int2 se = g_edge[i];
            a0 += __ldg(&g_u[se.x * 64 + lane]);
            a1 += __ldg(&g_u[se.x * 64 + lane + 32]);
            if (lane < 16) aef += __ldg(&ef[se.y * 16 + lane]);
        }
        a0 += b0; a1 += b1; aef += bef;

        float dg = dgv[m];
        float y0 = a0 + g_p[n * 64 + lane]      + dg * g_q[n * 64 + lane];
        float y1 = a1 + g_p[n * 64 + lane + 32] + dg * g_q[n * 64 + lane + 32];

        #pragma unroll
        for (int k = 0; k < 16; k++) {
            float mk = __shfl_sync(0xffffffffu, aef, k);
            y0 = fmaf(mk, sW1cT[k * 64 + lane],      y0);
            y1 = fmaf(mk, sW1cT[k * 64 + lane + 32], y1);
        }
        sY[warp][m * 64 + lane]      = fmaxf(y0, 0.f);
        sY[warp][m * 64 + lane + 32] = fmaxf(y1, 0.f);
    }
    __syncwarp();

    float o0[4] = {0.f, 0.f, 0.f, 0.f};
    float o1[4] = {0.f, 0.f, 0.f, 0.f};
    #pragma unroll
    for (int j = 0; j < 64; j++) {
        float w0 = sW2T[j * 64 + lane];
        float w1 = sW2T[j * 64 + lane + 32];
        #pragma unroll
        for (int m = 0; m < 4; m++) {
            float yj = sY[warp][m * 64 + j];
            o0[m] = fmaf(yj, w0, o0[m]);
            o1[m] = fmaf(yj, w1, o1[m]);
        }
    }

    for (int m = 0; m < cnt; m++) {
        int n = nb + m;
        if (dgv[m] > 0.f) {
            out[n * 64 + lane]      = o0[m];
            out[n * 64 + lane + 32] = o1[m];
        } else {
            out[n * 64 + lane]      = h[n * 64 + lane];
            out[n * 64 + lane + 32] = h[n * 64 + lane + 32];
        }
    }
}

// ---------------------------------------------------------------------------
extern "C" void kernel_launch(void* const* d_in, const int* in_sizes, int n_in,
                              void* d_out, int out_size)
{
    const float* h  = (const float*)d_in[0];
    const float* nf = (const float*)d_in[1];
    const float* ef = (const float*)d_in[2];
    const int*  src = (const int*)d_in[3];
    const int*  dst = (const int*)d_in[4];
    const float* W1 = (const float*)d_in[5];
    const float* W2 = (const float*)d_in[6];
    float* out = (float*)d_out;

    int N = in_sizes[1] / 32;   // nf is [N, 32]
    int E = in_sizes[3];        // src is [E]

    int ge   = (E + 255) / 256;
    int gsc  = (NN + 1023) / 1024;   // 49
    int gpq  = (N + 63) / 64;
    int gu   = (N + 127) / 128;
    int gf   = (N + 31) / 32;

    prep_kernel<<<148, 256>>>(W1, W2);
    hist_kernel<<<ge, 256>>>(dst, E);
    scan1_kernel<<<gsc, 1024>>>();
    scan2_kernel<<<gsc, 1024>>>(E);
    scatter_kernel<<<ge, 256>>>(src, dst, E);
    pq_kernel<<<gpq, 256>>>(nf, N);
    u_kernel<<<gu, 256>>>(h, N);
    gather_finalize_kernel<<<gf, 256>>>(h, ef, out, N);
}